// round 1
// baseline (speedup 1.0000x reference)
#include <cuda_runtime.h>
#include <cstdio>

#define NTOK   343
#define NWIN   256
#define NHEADS 12
#define HDIM   32
#define CDIM   384
#define MROWS  (NWIN * NTOK)     // 87808
#define QKVC   (3 * CDIM)        // 1152

// ---------------- scratch (static device globals; no allocation allowed) ----
__device__ float g_qkv[(size_t)MROWS * QKVC];      // ~404 MB
__device__ float g_att[(size_t)MROWS * CDIM];      // ~135 MB
__device__ float g_bias[NHEADS * NTOK * NTOK];     // ~5.6 MB

// ---------------- generic tiled fp32 GEMM: C = A[MxK] @ W[KxN] + bias[N] ----
// BM=BN=128, BK=16, 256 threads, 8x8 per thread. M%128==0, N%128==0, K%16==0.
__global__ __launch_bounds__(256) void gemm_bias_kernel(
    const float* __restrict__ A, const float* __restrict__ W,
    const float* __restrict__ bias, float* __restrict__ C,
    int M, int N, int K)
{
    __shared__ float As[16][132];   // padded: conflict-light stores, float4 loads
    __shared__ float Ws[16][128];

    const int bm = blockIdx.y * 128;
    const int bn = blockIdx.x * 128;
    const int tid = threadIdx.x;
    const int tx = tid & 15;        // 16 cols of 8
    const int ty = tid >> 4;        // 16 rows of 8

    float acc[8][8];
#pragma unroll
    for (int i = 0; i < 8; ++i)
#pragma unroll
        for (int j = 0; j < 8; ++j) acc[i][j] = 0.f;

    for (int k0 = 0; k0 < K; k0 += 16) {
#pragma unroll
        for (int s = 0; s < 2; ++s) {
            int vi = tid + s * 256;          // 0..511 float4 slots
            // A tile: 128 rows x 16 k
            int r  = vi >> 2;
            int c4 = (vi & 3) << 2;
            float4 av = *reinterpret_cast<const float4*>(
                &A[(size_t)(bm + r) * K + k0 + c4]);
            As[c4 + 0][r] = av.x;
            As[c4 + 1][r] = av.y;
            As[c4 + 2][r] = av.z;
            As[c4 + 3][r] = av.w;
            // W tile: 16 rows x 128 cols
            int rw = vi >> 5;
            int cw = (vi & 31) << 2;
            *reinterpret_cast<float4*>(&Ws[rw][cw]) =
                *reinterpret_cast<const float4*>(&W[(size_t)(k0 + rw) * N + bn + cw]);
        }
        __syncthreads();

#pragma unroll
        for (int kk = 0; kk < 16; ++kk) {
            float4 a0 = *reinterpret_cast<const float4*>(&As[kk][ty * 8]);
            float4 a1 = *reinterpret_cast<const float4*>(&As[kk][ty * 8 + 4]);
            float4 w0 = *reinterpret_cast<const float4*>(&Ws[kk][tx * 8]);
            float4 w1 = *reinterpret_cast<const float4*>(&Ws[kk][tx * 8 + 4]);
            float a[8] = {a0.x, a0.y, a0.z, a0.w, a1.x, a1.y, a1.z, a1.w};
            float w[8] = {w0.x, w0.y, w0.z, w0.w, w1.x, w1.y, w1.z, w1.w};
#pragma unroll
            for (int i = 0; i < 8; ++i)
#pragma unroll
                for (int j = 0; j < 8; ++j)
                    acc[i][j] += a[i] * w[j];
        }
        __syncthreads();
    }

#pragma unroll
    for (int i = 0; i < 8; ++i) {
        int row = bm + ty * 8 + i;
#pragma unroll
        for (int j4 = 0; j4 < 2; ++j4) {
            int col = bn + tx * 8 + j4 * 4;
            float4 o;
            o.x = acc[i][j4 * 4 + 0] + bias[col + 0];
            o.y = acc[i][j4 * 4 + 1] + bias[col + 1];
            o.z = acc[i][j4 * 4 + 2] + bias[col + 2];
            o.w = acc[i][j4 * 4 + 3] + bias[col + 3];
            *reinterpret_cast<float4*>(&C[(size_t)row * N + col]) = o;
        }
    }
}

// ---------------- expand bias_table via rel_pos_index -> [NH][343][343] ------
__global__ void bias_expand_kernel(const float* __restrict__ bt,
                                   const int* __restrict__ ridx,
                                   float* __restrict__ bf)
{
    int idx = blockIdx.x * blockDim.x + threadIdx.x;
    const int per_head = NTOK * NTOK;          // 117649
    if (idx < NHEADS * per_head) {
        int h  = idx / per_head;
        int ij = idx - h * per_head;
        bf[idx] = bt[ridx[ij] * NHEADS + h];
    }
}

// ---------------- fused per-head attention with online softmax ---------------
// grid (6, 12, 256), block 64. One thread = one query row. K/V/bias tiled in smem.
__global__ __launch_bounds__(64) void attn_kernel(
    const float* __restrict__ qkv, const float* __restrict__ bias_full,
    float* __restrict__ out)
{
    const int qt  = blockIdx.x;
    const int h   = blockIdx.y;
    const int b   = blockIdx.z;
    const int tid = threadIdx.x;

    __shared__ float4 ks4[64][8];
    __shared__ float4 vs4[64][8];
    __shared__ float  bs[64][65];     // padded: bs[tid][j] conflict-free

    const int  qi = qt * 64 + tid;
    const bool active = qi < NTOK;
    const float* base = qkv + (size_t)b * NTOK * QKVC;

    float4 q4[8];
    if (active) {
        const float4* qp = reinterpret_cast<const float4*>(
            base + (size_t)qi * QKVC + h * HDIM);
        const float sc = 0.17677669529663687f;   // 1/sqrt(32)
#pragma unroll
        for (int w = 0; w < 8; ++w) {
            float4 t = qp[w];
            t.x *= sc; t.y *= sc; t.z *= sc; t.w *= sc;
            q4[w] = t;
        }
    }

    float m = -1e30f, l = 0.f;
    float4 o4[8];
#pragma unroll
    for (int w = 0; w < 8; ++w) o4[w] = make_float4(0.f, 0.f, 0.f, 0.f);

    const float* brow = bias_full + ((size_t)h * NTOK + qt * 64) * NTOK;

    for (int j0 = 0; j0 < NTOK; j0 += 64) {
        const int jn = min(64, NTOK - j0);
        __syncthreads();
        // K/V tiles: 512 float4 each, coalesced (8 lanes = 128B per row)
#pragma unroll
        for (int s = 0; s < 8; ++s) {
            int f = tid + s * 64;
            int j = f >> 3, w = f & 7;
            if (j < jn) {
                const float* rowp = base + (size_t)(j0 + j) * QKVC + h * HDIM;
                ks4[j][w] = reinterpret_cast<const float4*>(rowp + CDIM)[w];
                vs4[j][w] = reinterpret_cast<const float4*>(rowp + 2 * CDIM)[w];
            }
        }
        // bias tile: coalesced along j
        for (int e = tid; e < 64 * 64; e += 64) {
            int r = e >> 6, j = e & 63;
            bs[r][j] = ((qt * 64 + r) < NTOK && j < jn)
                           ? brow[(size_t)r * NTOK + j0 + j] : 0.f;
        }
        __syncthreads();

        if (active) {
            int c0 = 0;
            // full 16-wide chunks: scores in registers, amortized rescale
            for (; c0 + 16 <= jn; c0 += 16) {
                float s[16];
#pragma unroll
                for (int jj = 0; jj < 16; ++jj) {
                    int j = c0 + jj;
                    float d0 = 0.f, d1 = 0.f;
#pragma unroll
                    for (int w = 0; w < 8; w += 2) {
                        float4 k0 = ks4[j][w], k1 = ks4[j][w + 1];
                        d0 += q4[w].x * k0.x + q4[w].y * k0.y
                            + q4[w].z * k0.z + q4[w].w * k0.w;
                        d1 += q4[w + 1].x * k1.x + q4[w + 1].y * k1.y
                            + q4[w + 1].z * k1.z + q4[w + 1].w * k1.w;
                    }
                    s[jj] = d0 + d1 + bs[tid][j];
                }
                float cm = fmaxf(m, s[0]);
#pragma unroll
                for (int jj = 1; jj < 16; ++jj) cm = fmaxf(cm, s[jj]);
                float corr = __expf(m - cm);
                m = cm;
                l *= corr;
#pragma unroll
                for (int w = 0; w < 8; ++w) {
                    o4[w].x *= corr; o4[w].y *= corr;
                    o4[w].z *= corr; o4[w].w *= corr;
                }
#pragma unroll
                for (int jj = 0; jj < 16; ++jj) {
                    float p = __expf(s[jj] - cm);
                    l += p;
#pragma unroll
                    for (int w = 0; w < 8; ++w) {
                        float4 v = vs4[c0 + jj][w];
                        o4[w].x += p * v.x; o4[w].y += p * v.y;
                        o4[w].z += p * v.z; o4[w].w += p * v.w;
                    }
                }
            }
            // remainder (only last 7 of the final tile): per-j online update
            for (int j = c0; j < jn; ++j) {
                float d0 = 0.f, d1 = 0.f;
#pragma unroll
                for (int w = 0; w < 8; w += 2) {
                    float4 k0 = ks4[j][w], k1 = ks4[j][w + 1];
                    d0 += q4[w].x * k0.x + q4[w].y * k0.y
                        + q4[w].z * k0.z + q4[w].w * k0.w;
                    d1 += q4[w + 1].x * k1.x + q4[w + 1].y * k1.y
                        + q4[w + 1].z * k1.z + q4[w + 1].w * k1.w;
                }
                float sv = d0 + d1 + bs[tid][j];
                float mn = fmaxf(m, sv);
                float corr = __expf(m - mn);
                float p = __expf(sv - mn);
                l = l * corr + p;
#pragma unroll
                for (int w = 0; w < 8; ++w) {
                    float4 v = vs4[j][w];
                    o4[w].x = o4[w].x * corr + p * v.x;
                    o4[w].y = o4[w].y * corr + p * v.y;
                    o4[w].z = o4[w].z * corr + p * v.z;
                    o4[w].w = o4[w].w * corr + p * v.w;
                }
                m = mn;
            }
        }
    }

    if (active) {
        float inv = 1.f / l;
        float4* op = reinterpret_cast<float4*>(
            out + ((size_t)b * NTOK + qi) * CDIM + h * HDIM);
#pragma unroll
        for (int w = 0; w < 8; ++w) {
            float4 t = o4[w];
            t.x *= inv; t.y *= inv; t.z *= inv; t.w *= inv;
            op[w] = t;
        }
    }
}

// ---------------- launch ------------------------------------------------------
extern "C" void kernel_launch(void* const* d_in, const int* in_sizes, int n_in,
                              void* d_out, int out_size)
{
    const float* x       = (const float*)d_in[0];
    const float* qkv_w   = (const float*)d_in[1];
    const float* qkv_b   = (const float*)d_in[2];
    const float* proj_w  = (const float*)d_in[3];
    const float* proj_b  = (const float*)d_in[4];
    const float* bt      = (const float*)d_in[5];
    const int*   ridx    = (const int*)d_in[6];
    float*       out     = (float*)d_out;

    void *p_qkv, *p_att, *p_bias;
    cudaGetSymbolAddress(&p_qkv,  g_qkv);
    cudaGetSymbolAddress(&p_att,  g_att);
    cudaGetSymbolAddress(&p_bias, g_bias);
    float* qkv  = (float*)p_qkv;
    float* att  = (float*)p_att;
    float* bias = (float*)p_bias;

    // 1) QKV projection: [87808,384] @ [384,1152] + b
    gemm_bias_kernel<<<dim3(QKVC / 128, MROWS / 128), 256>>>(
        x, qkv_w, qkv_b, qkv, MROWS, QKVC, CDIM);

    // 2) expand relative-position bias per head
    {
        int total = NHEADS * NTOK * NTOK;
        bias_expand_kernel<<<(total + 255) / 256, 256>>>(bt, ridx, bias);
    }

    // 3) fused attention (QK^T + bias + softmax + PV)
    attn_kernel<<<dim3((NTOK + 63) / 64, NHEADS, NWIN), 64>>>(qkv, bias, att);

    // 4) output projection: [87808,384] @ [384,384] + b
    gemm_bias_kernel<<<dim3(CDIM / 128, MROWS / 128), 256>>>(
        att, proj_w, proj_b, out, MROWS, CDIM, CDIM);
}

// round 3
// speedup vs baseline: 1.4861x; 1.4861x over previous
#include <cuda_runtime.h>
#include <cstdint>
#include <cstdio>

#define NTOK   343
#define NWIN   256
#define NHEADS 12
#define HDIM   32
#define CDIM   384
#define MROWS  (NWIN * NTOK)     // 87808
#define QKVC   (3 * CDIM)        // 1152

// ---------------- scratch (static device globals; no allocation allowed) ----
__device__ float g_qkv[(size_t)MROWS * QKVC];        // qkv activations
__device__ float g_att[(size_t)MROWS * CDIM];        // attention output (tf32-rounded)
__device__ float g_bias[NHEADS * NTOK * NTOK];       // expanded rel-pos bias
__device__ float g_xr[(size_t)MROWS * CDIM];         // tf32-rounded x
__device__ float g_wqt[(size_t)QKVC * CDIM];         // qkv_w transposed+rounded [1152][384]
__device__ float g_wpt[(size_t)CDIM * CDIM];         // proj_w transposed+rounded [384][384]

// ======================= helpers ============================================
__device__ __forceinline__ float tf32_rna(float v) {
    uint32_t u;
    asm("cvt.rna.tf32.f32 %0, %1;" : "=r"(u) : "f"(v));
    return __uint_as_float(u);
}
#define CP_ASYNC16(dst, src) \
    asm volatile("cp.async.cg.shared.global [%0], [%1], 16;" :: "r"(dst), "l"(src))
#define CP_COMMIT() asm volatile("cp.async.commit_group;" ::: "memory")
#define CP_WAIT1()  asm volatile("cp.async.wait_group 1;" ::: "memory")
#define CP_WAIT0()  asm volatile("cp.async.wait_group 0;" ::: "memory")

__device__ __forceinline__ uint32_t smem_u32(const void* p) {
    uint32_t a;
    asm("{ .reg .u64 t; cvta.to.shared.u64 t, %1; cvt.u32.u64 %0, t; }" : "=r"(a) : "l"(p));
    return a;
}

__device__ __forceinline__ void mma_tf32(float* c, const uint32_t* a, const uint32_t* b) {
    asm volatile(
        "mma.sync.aligned.m16n8k8.row.col.f32.tf32.tf32.f32 "
        "{%0,%1,%2,%3}, {%4,%5,%6,%7}, {%8,%9}, {%0,%1,%2,%3};"
        : "+f"(c[0]), "+f"(c[1]), "+f"(c[2]), "+f"(c[3])
        : "r"(a[0]), "r"(a[1]), "r"(a[2]), "r"(a[3]), "r"(b[0]), "r"(b[1]));
}

// ======================= prep kernels =======================================
__global__ void round_tf32_kernel(const float* __restrict__ in, float* __restrict__ out, int n4) {
    int i = blockIdx.x * blockDim.x + threadIdx.x;
    if (i < n4) {
        float4 v = reinterpret_cast<const float4*>(in)[i];
        v.x = tf32_rna(v.x); v.y = tf32_rna(v.y);
        v.z = tf32_rna(v.z); v.w = tf32_rna(v.w);
        reinterpret_cast<float4*>(out)[i] = v;
    }
}

// W[K][Nw] -> Wt[Nw][K], tf32-rounded. block (32,8), grid (Nw/32, K/32)
__global__ void transpose_round_kernel(const float* __restrict__ W, float* __restrict__ Wt,
                                       int K, int Nw) {
    __shared__ float t[32][33];
    int n0 = blockIdx.x * 32, k0 = blockIdx.y * 32;
#pragma unroll
    for (int s = 0; s < 4; ++s) {
        int k = k0 + threadIdx.y + s * 8;
        t[threadIdx.y + s * 8][threadIdx.x] = tf32_rna(W[(size_t)k * Nw + n0 + threadIdx.x]);
    }
    __syncthreads();
#pragma unroll
    for (int s = 0; s < 4; ++s) {
        int n = n0 + threadIdx.y + s * 8;
        Wt[(size_t)n * K + k0 + threadIdx.x] = t[threadIdx.x][threadIdx.y + s * 8];
    }
}

// ======================= mma.sync TF32 GEMM =================================
// C[M,Ntot] = A[M,384] @ Wt[Ntot,384]^T + bias.
// CTA 128x128, BK=32, 256 threads (8 warps: 2m x 4n), warp tile 64x32.
// SMEM tiles padded to 36 floats/row: conflict-free frag loads AND 16B-aligned
// cp.async rows (36 floats = 144 B = 9*16 B).
#define GK      384
#define GNCHUNK 12
#define LDT     36
#define TILE_B  (128 * LDT * 4)      // 18432 bytes per tile buffer
#define GSM_TOT (4 * TILE_B)         // 73728

__global__ __launch_bounds__(256) void mma_gemm_kernel(
    const float* __restrict__ A, const float* __restrict__ Wt,
    const float* __restrict__ bias, float* __restrict__ C, int Ntot)
{
    extern __shared__ float sm[];
    float* sA[2] = { sm,               sm + 128 * LDT };
    float* sB[2] = { sm + 2*128*LDT,   sm + 3*128*LDT };
    const uint32_t sAu[2] = { smem_u32(sA[0]), smem_u32(sA[1]) };
    const uint32_t sBu[2] = { smem_u32(sB[0]), smem_u32(sB[1]) };

    const int tid = threadIdx.x;
    const int wid = tid >> 5, lid = tid & 31;
    const int g = lid >> 2, t4 = lid & 3;
    const int wm = (wid & 1) * 64;       // warp m offset
    const int wn = (wid >> 1) * 32;      // warp n offset
    const int bm = blockIdx.y * 128;
    const int bn = blockIdx.x * 128;

    float acc[4][4][4];
#pragma unroll
    for (int i = 0; i < 4; ++i)
#pragma unroll
        for (int j = 0; j < 4; ++j)
#pragma unroll
            for (int q = 0; q < 4; ++q) acc[i][j][q] = 0.f;

    // chunk loader: A rows [bm,128), B rows [bn,128), cols [c*32, +32)
    auto load_chunk = [&](int c, int buf) {
        const float* ap = A  + (size_t)bm * GK + c * 32;
        const float* bp = Wt + (size_t)bn * GK + c * 32;
#pragma unroll
        for (int i = 0; i < 4; ++i) {
            int f = tid + i * 256;           // 1024 float4 slots
            int row = f >> 3, c4 = (f & 7) * 4;
            CP_ASYNC16(sAu[buf] + (uint32_t)(row * LDT + c4) * 4,
                       ap + (size_t)row * GK + c4);
        }
#pragma unroll
        for (int i = 0; i < 4; ++i) {
            int f = tid + i * 256;
            int row = f >> 3, c4 = (f & 7) * 4;
            CP_ASYNC16(sBu[buf] + (uint32_t)(row * LDT + c4) * 4,
                       bp + (size_t)row * GK + c4);
        }
    };

    load_chunk(0, 0);
    CP_COMMIT();

    for (int c = 0; c < GNCHUNK; ++c) {
        const int b = c & 1;
        if (c + 1 < GNCHUNK) {
            load_chunk(c + 1, b ^ 1);
            CP_COMMIT();
            CP_WAIT1();
        } else {
            CP_WAIT0();
        }
        __syncthreads();

        const float* As = sA[b];
        const float* Bs = sB[b];
#pragma unroll
        for (int ks = 0; ks < 4; ++ks) {
            const int k = ks * 8 + t4;
            uint32_t af[4][4], bf[4][2];
#pragma unroll
            for (int mi = 0; mi < 4; ++mi) {
                const int r = wm + mi * 16 + g;
                af[mi][0] = __float_as_uint(As[r * LDT + k]);
                af[mi][1] = __float_as_uint(As[(r + 8) * LDT + k]);
                af[mi][2] = __float_as_uint(As[r * LDT + k + 4]);
                af[mi][3] = __float_as_uint(As[(r + 8) * LDT + k + 4]);
            }
#pragma unroll
            for (int ni = 0; ni < 4; ++ni) {
                const int n = wn + ni * 8 + g;
                bf[ni][0] = __float_as_uint(Bs[n * LDT + k]);
                bf[ni][1] = __float_as_uint(Bs[n * LDT + k + 4]);
            }
#pragma unroll
            for (int mi = 0; mi < 4; ++mi)
#pragma unroll
                for (int ni = 0; ni < 4; ++ni)
                    mma_tf32(acc[mi][ni], af[mi], bf[ni]);
        }
        __syncthreads();
    }

    // epilogue: each thread owns 2 floats x 2 row-halves per (mi,ni)
#pragma unroll
    for (int mi = 0; mi < 4; ++mi) {
#pragma unroll
        for (int ni = 0; ni < 4; ++ni) {
            const int row = bm + wm + mi * 16 + g;
            const int col = bn + wn + ni * 8 + t4 * 2;
            const float b0 = __ldg(&bias[col]), b1 = __ldg(&bias[col + 1]);
            float2 v0 = { acc[mi][ni][0] + b0, acc[mi][ni][1] + b1 };
            float2 v1 = { acc[mi][ni][2] + b0, acc[mi][ni][3] + b1 };
            *reinterpret_cast<float2*>(&C[(size_t)row * Ntot + col]) = v0;
            *reinterpret_cast<float2*>(&C[(size_t)(row + 8) * Ntot + col]) = v1;
        }
    }
}

// ---------------- expand bias_table via rel_pos_index -> [NH][343][343] ------
__global__ void bias_expand_kernel(const float* __restrict__ bt,
                                   const int* __restrict__ ridx,
                                   float* __restrict__ bf)
{
    int idx = blockIdx.x * blockDim.x + threadIdx.x;
    const int per_head = NTOK * NTOK;
    if (idx < NHEADS * per_head) {
        int h  = idx / per_head;
        int ij = idx - h * per_head;
        bf[idx] = bt[ridx[ij] * NHEADS + h];
    }
}

// ---------------- fused per-head attention with online softmax ---------------
__global__ __launch_bounds__(64) void attn_kernel(
    const float* __restrict__ qkv, const float* __restrict__ bias_full,
    float* __restrict__ out)
{
    const int qt  = blockIdx.x;
    const int h   = blockIdx.y;
    const int b   = blockIdx.z;
    const int tid = threadIdx.x;

    __shared__ float4 ks4[64][8];
    __shared__ float4 vs4[64][8];
    __shared__ float  bs[64][65];

    const int  qi = qt * 64 + tid;
    const bool active = qi < NTOK;
    const float* base = qkv + (size_t)b * NTOK * QKVC;

    float4 q4[8];
    if (active) {
        const float4* qp = reinterpret_cast<const float4*>(
            base + (size_t)qi * QKVC + h * HDIM);
        const float sc = 0.17677669529663687f;
#pragma unroll
        for (int w = 0; w < 8; ++w) {
            float4 t = qp[w];
            t.x *= sc; t.y *= sc; t.z *= sc; t.w *= sc;
            q4[w] = t;
        }
    }

    float m = -1e30f, l = 0.f;
    float4 o4[8];
#pragma unroll
    for (int w = 0; w < 8; ++w) o4[w] = make_float4(0.f, 0.f, 0.f, 0.f);

    const float* brow = bias_full + ((size_t)h * NTOK + qt * 64) * NTOK;

    for (int j0 = 0; j0 < NTOK; j0 += 64) {
        const int jn = min(64, NTOK - j0);
        __syncthreads();
#pragma unroll
        for (int s = 0; s < 8; ++s) {
            int f = tid + s * 64;
            int j = f >> 3, w = f & 7;
            if (j < jn) {
                const float* rowp = base + (size_t)(j0 + j) * QKVC + h * HDIM;
                ks4[j][w] = reinterpret_cast<const float4*>(rowp + CDIM)[w];
                vs4[j][w] = reinterpret_cast<const float4*>(rowp + 2 * CDIM)[w];
            }
        }
        for (int e = tid; e < 64 * 64; e += 64) {
            int r = e >> 6, j = e & 63;
            bs[r][j] = ((qt * 64 + r) < NTOK && j < jn)
                           ? brow[(size_t)r * NTOK + j0 + j] : 0.f;
        }
        __syncthreads();

        if (active) {
            int c0 = 0;
            for (; c0 + 16 <= jn; c0 += 16) {
                float s[16];
#pragma unroll
                for (int jj = 0; jj < 16; ++jj) {
                    int j = c0 + jj;
                    float d0 = 0.f, d1 = 0.f;
#pragma unroll
                    for (int w = 0; w < 8; w += 2) {
                        float4 k0 = ks4[j][w], k1 = ks4[j][w + 1];
                        d0 += q4[w].x * k0.x + q4[w].y * k0.y
                            + q4[w].z * k0.z + q4[w].w * k0.w;
                        d1 += q4[w + 1].x * k1.x + q4[w + 1].y * k1.y
                            + q4[w + 1].z * k1.z + q4[w + 1].w * k1.w;
                    }
                    s[jj] = d0 + d1 + bs[tid][j];
                }
                float cm = fmaxf(m, s[0]);
#pragma unroll
                for (int jj = 1; jj < 16; ++jj) cm = fmaxf(cm, s[jj]);
                float corr = __expf(m - cm);
                m = cm;
                l *= corr;
#pragma unroll
                for (int w = 0; w < 8; ++w) {
                    o4[w].x *= corr; o4[w].y *= corr;
                    o4[w].z *= corr; o4[w].w *= corr;
                }
#pragma unroll
                for (int jj = 0; jj < 16; ++jj) {
                    float p = __expf(s[jj] - cm);
                    l += p;
#pragma unroll
                    for (int w = 0; w < 8; ++w) {
                        float4 v = vs4[c0 + jj][w];
                        o4[w].x += p * v.x; o4[w].y += p * v.y;
                        o4[w].z += p * v.z; o4[w].w += p * v.w;
                    }
                }
            }
            for (int j = c0; j < jn; ++j) {
                float d0 = 0.f, d1 = 0.f;
#pragma unroll
                for (int w = 0; w < 8; w += 2) {
                    float4 k0 = ks4[j][w], k1 = ks4[j][w + 1];
                    d0 += q4[w].x * k0.x + q4[w].y * k0.y
                        + q4[w].z * k0.z + q4[w].w * k0.w;
                    d1 += q4[w + 1].x * k1.x + q4[w + 1].y * k1.y
                        + q4[w + 1].z * k1.z + q4[w + 1].w * k1.w;
                }
                float sv = d0 + d1 + bs[tid][j];
                float mn = fmaxf(m, sv);
                float corr = __expf(m - mn);
                float p = __expf(sv - mn);
                l = l * corr + p;
#pragma unroll
                for (int w = 0; w < 8; ++w) {
                    float4 v = vs4[j][w];
                    o4[w].x = o4[w].x * corr + p * v.x;
                    o4[w].y = o4[w].y * corr + p * v.y;
                    o4[w].z = o4[w].z * corr + p * v.z;
                    o4[w].w = o4[w].w * corr + p * v.w;
                }
                m = mn;
            }
        }
    }

    if (active) {
        float inv = 1.f / l;
        float4* op = reinterpret_cast<float4*>(
            out + ((size_t)b * NTOK + qi) * CDIM + h * HDIM);
#pragma unroll
        for (int w = 0; w < 8; ++w) {
            float4 t = o4[w];
            // tf32-round: this tensor is the A operand of the proj GEMM
            t.x = tf32_rna(t.x * inv); t.y = tf32_rna(t.y * inv);
            t.z = tf32_rna(t.z * inv); t.w = tf32_rna(t.w * inv);
            op[w] = t;
        }
    }
}

// ---------------- launch ------------------------------------------------------
extern "C" void kernel_launch(void* const* d_in, const int* in_sizes, int n_in,
                              void* d_out, int out_size)
{
    const float* x       = (const float*)d_in[0];
    const float* qkv_w   = (const float*)d_in[1];
    const float* qkv_b   = (const float*)d_in[2];
    const float* proj_w  = (const float*)d_in[3];
    const float* proj_b  = (const float*)d_in[4];
    const float* bt      = (const float*)d_in[5];
    const int*   ridx    = (const int*)d_in[6];
    float*       out     = (float*)d_out;

    void *p_qkv, *p_att, *p_bias, *p_xr, *p_wqt, *p_wpt;
    cudaGetSymbolAddress(&p_qkv,  g_qkv);
    cudaGetSymbolAddress(&p_att,  g_att);
    cudaGetSymbolAddress(&p_bias, g_bias);
    cudaGetSymbolAddress(&p_xr,   g_xr);
    cudaGetSymbolAddress(&p_wqt,  g_wqt);
    cudaGetSymbolAddress(&p_wpt,  g_wpt);
    float* qkv  = (float*)p_qkv;
    float* att  = (float*)p_att;
    float* bias = (float*)p_bias;
    float* xr   = (float*)p_xr;
    float* wqt  = (float*)p_wqt;
    float* wpt  = (float*)p_wpt;

    cudaFuncSetAttribute(mma_gemm_kernel,
                         cudaFuncAttributeMaxDynamicSharedMemorySize, GSM_TOT);

    // 0) prep: tf32-round x; transpose+round weights; expand bias
    {
        int n4 = MROWS * CDIM / 4;
        round_tf32_kernel<<<(n4 + 255) / 256, 256>>>(x, xr, n4);
        transpose_round_kernel<<<dim3(QKVC / 32, CDIM / 32), dim3(32, 8)>>>(qkv_w, wqt, CDIM, QKVC);
        transpose_round_kernel<<<dim3(CDIM / 32, CDIM / 32), dim3(32, 8)>>>(proj_w, wpt, CDIM, CDIM);
        int total = NHEADS * NTOK * NTOK;
        bias_expand_kernel<<<(total + 255) / 256, 256>>>(bt, ridx, bias);
    }

    // 1) QKV projection (tensor cores via mma.sync tf32)
    mma_gemm_kernel<<<dim3(QKVC / 128, MROWS / 128), 256, GSM_TOT>>>(xr, wqt, qkv_b, qkv, QKVC);

    // 2) fused attention (QK^T + bias + softmax + PV)
    attn_kernel<<<dim3((NTOK + 63) / 64, NHEADS, NWIN), 64>>>(qkv, bias, att);

    // 3) output projection (tensor cores via mma.sync tf32)
    mma_gemm_kernel<<<dim3(CDIM / 128, MROWS / 128), 256, GSM_TOT>>>(att, wpt, proj_b, out, CDIM);
}

// round 5
// speedup vs baseline: 2.5552x; 1.7195x over previous
#include <cuda_runtime.h>
#include <cstdint>
#include <cstdio>

#define NTOK   343
#define NWIN   256
#define NHEADS 12
#define HDIM   32
#define CDIM   384
#define MROWS  (NWIN * NTOK)     // 87808
#define QKVC   (3 * CDIM)        // 1152
#define NPAD   352               // 343 padded to 11*32
#define KPAD   384               // 343 padded to 6*64

// ---------------- scratch (static device globals; no allocation allowed) ----
__device__ float g_qkv[(size_t)MROWS * QKVC];        // qkv activations
__device__ float g_att[(size_t)MROWS * CDIM];        // attention output (tf32-rounded)
__device__ float g_bias[NHEADS * NPAD * KPAD];       // padded rel-pos bias (+ -1e30 pad keys)
__device__ float g_xr[(size_t)MROWS * CDIM];         // tf32-rounded x
__device__ float g_wqt[(size_t)QKVC * CDIM];         // qkv_w transposed+rounded
__device__ float g_wpt[(size_t)CDIM * CDIM];         // proj_w transposed+rounded

// ======================= helpers ============================================
__device__ __forceinline__ float tf32_rna(float v) {
    uint32_t u;
    asm("cvt.rna.tf32.f32 %0, %1;" : "=r"(u) : "f"(v));
    return __uint_as_float(u);
}
__device__ __forceinline__ uint32_t tf32u(float v) {
    uint32_t u;
    asm("cvt.rna.tf32.f32 %0, %1;" : "=r"(u) : "f"(v));
    return u;
}
#define CP_ASYNC16(dst, src) \
    asm volatile("cp.async.cg.shared.global [%0], [%1], 16;" :: "r"(dst), "l"(src))
#define CP_COMMIT() asm volatile("cp.async.commit_group;" ::: "memory")
#define CP_WAIT1()  asm volatile("cp.async.wait_group 1;" ::: "memory")
#define CP_WAIT0()  asm volatile("cp.async.wait_group 0;" ::: "memory")

__device__ __forceinline__ uint32_t smem_u32(const void* p) {
    uint32_t a;
    asm("{ .reg .u64 t; cvta.to.shared.u64 t, %1; cvt.u32.u64 %0, t; }" : "=r"(a) : "l"(p));
    return a;
}

__device__ __forceinline__ void mma_tf32(float* c, const uint32_t* a, const uint32_t* b) {
    asm volatile(
        "mma.sync.aligned.m16n8k8.row.col.f32.tf32.tf32.f32 "
        "{%0,%1,%2,%3}, {%4,%5,%6,%7}, {%8,%9}, {%0,%1,%2,%3};"
        : "+f"(c[0]), "+f"(c[1]), "+f"(c[2]), "+f"(c[3])
        : "r"(a[0]), "r"(a[1]), "r"(a[2]), "r"(a[3]), "r"(b[0]), "r"(b[1]));
}

// ======================= prep kernels =======================================
__global__ void round_tf32_kernel(const float* __restrict__ in, float* __restrict__ out, int n4) {
    int i = blockIdx.x * blockDim.x + threadIdx.x;
    if (i < n4) {
        float4 v = reinterpret_cast<const float4*>(in)[i];
        v.x = tf32_rna(v.x); v.y = tf32_rna(v.y);
        v.z = tf32_rna(v.z); v.w = tf32_rna(v.w);
        reinterpret_cast<float4*>(out)[i] = v;
    }
}

__global__ void transpose_round_kernel(const float* __restrict__ W, float* __restrict__ Wt,
                                       int K, int Nw) {
    __shared__ float t[32][33];
    int n0 = blockIdx.x * 32, k0 = blockIdx.y * 32;
#pragma unroll
    for (int s = 0; s < 4; ++s) {
        int k = k0 + threadIdx.y + s * 8;
        t[threadIdx.y + s * 8][threadIdx.x] = tf32_rna(W[(size_t)k * Nw + n0 + threadIdx.x]);
    }
    __syncthreads();
#pragma unroll
    for (int s = 0; s < 4; ++s) {
        int n = n0 + threadIdx.y + s * 8;
        Wt[(size_t)n * K + k0 + threadIdx.x] = t[threadIdx.x][threadIdx.y + s * 8];
    }
}

// padded bias: [12][352][384]; pad keys -> -1e30 (softmax zero), pad rows -> 0
__global__ void bias_expand_pad_kernel(const float* __restrict__ bt,
                                       const int* __restrict__ ridx,
                                       float* __restrict__ bf)
{
    int idx = blockIdx.x * blockDim.x + threadIdx.x;
    if (idx < NHEADS * NPAD * KPAD) {
        int h   = idx / (NPAD * KPAD);
        int rem = idx - h * NPAD * KPAD;
        int r   = rem / KPAD;
        int k   = rem - r * KPAD;
        float v;
        if (k >= NTOK)      v = -1e30f;
        else if (r >= NTOK) v = 0.f;
        else                v = bt[ridx[r * NTOK + k] * NHEADS + h];
        bf[idx] = v;
    }
}

// ======================= mma.sync TF32 GEMM (unchanged from R3) =============
#define GK      384
#define GNCHUNK 12
#define LDT     36
#define GSM_TOT (4 * 128 * LDT * 4)

__global__ __launch_bounds__(256) void mma_gemm_kernel(
    const float* __restrict__ A, const float* __restrict__ Wt,
    const float* __restrict__ bias, float* __restrict__ C, int Ntot)
{
    extern __shared__ float sm[];
    float* sA[2] = { sm,               sm + 128 * LDT };
    float* sB[2] = { sm + 2*128*LDT,   sm + 3*128*LDT };
    const uint32_t sAu[2] = { smem_u32(sA[0]), smem_u32(sA[1]) };
    const uint32_t sBu[2] = { smem_u32(sB[0]), smem_u32(sB[1]) };

    const int tid = threadIdx.x;
    const int wid = tid >> 5, lid = tid & 31;
    const int g = lid >> 2, t4 = lid & 3;
    const int wm = (wid & 1) * 64;
    const int wn = (wid >> 1) * 32;
    const int bm = blockIdx.y * 128;
    const int bn = blockIdx.x * 128;

    float acc[4][4][4];
#pragma unroll
    for (int i = 0; i < 4; ++i)
#pragma unroll
        for (int j = 0; j < 4; ++j)
#pragma unroll
            for (int q = 0; q < 4; ++q) acc[i][j][q] = 0.f;

    auto load_chunk = [&](int c, int buf) {
        const float* ap = A  + (size_t)bm * GK + c * 32;
        const float* bp = Wt + (size_t)bn * GK + c * 32;
#pragma unroll
        for (int i = 0; i < 4; ++i) {
            int f = tid + i * 256;
            int row = f >> 3, c4 = (f & 7) * 4;
            CP_ASYNC16(sAu[buf] + (uint32_t)(row * LDT + c4) * 4,
                       ap + (size_t)row * GK + c4);
        }
#pragma unroll
        for (int i = 0; i < 4; ++i) {
            int f = tid + i * 256;
            int row = f >> 3, c4 = (f & 7) * 4;
            CP_ASYNC16(sBu[buf] + (uint32_t)(row * LDT + c4) * 4,
                       bp + (size_t)row * GK + c4);
        }
    };

    load_chunk(0, 0);
    CP_COMMIT();

    for (int c = 0; c < GNCHUNK; ++c) {
        const int b = c & 1;
        if (c + 1 < GNCHUNK) {
            load_chunk(c + 1, b ^ 1);
            CP_COMMIT();
            CP_WAIT1();
        } else {
            CP_WAIT0();
        }
        __syncthreads();

        const float* As = sA[b];
        const float* Bs = sB[b];
#pragma unroll
        for (int ks = 0; ks < 4; ++ks) {
            const int k = ks * 8 + t4;
            uint32_t af[4][4], bf[4][2];
#pragma unroll
            for (int mi = 0; mi < 4; ++mi) {
                const int r = wm + mi * 16 + g;
                af[mi][0] = __float_as_uint(As[r * LDT + k]);
                af[mi][1] = __float_as_uint(As[(r + 8) * LDT + k]);
                af[mi][2] = __float_as_uint(As[r * LDT + k + 4]);
                af[mi][3] = __float_as_uint(As[(r + 8) * LDT + k + 4]);
            }
#pragma unroll
            for (int ni = 0; ni < 4; ++ni) {
                const int n = wn + ni * 8 + g;
                bf[ni][0] = __float_as_uint(Bs[n * LDT + k]);
                bf[ni][1] = __float_as_uint(Bs[n * LDT + k + 4]);
            }
#pragma unroll
            for (int mi = 0; mi < 4; ++mi)
#pragma unroll
                for (int ni = 0; ni < 4; ++ni)
                    mma_tf32(acc[mi][ni], af[mi], bf[ni]);
        }
        __syncthreads();
    }

#pragma unroll
    for (int mi = 0; mi < 4; ++mi) {
#pragma unroll
        for (int ni = 0; ni < 4; ++ni) {
            const int row = bm + wm + mi * 16 + g;
            const int col = bn + wn + ni * 8 + t4 * 2;
            const float b0 = __ldg(&bias[col]), b1 = __ldg(&bias[col + 1]);
            float2 v0 = { acc[mi][ni][0] + b0, acc[mi][ni][1] + b1 };
            float2 v1 = { acc[mi][ni][2] + b0, acc[mi][ni][3] + b1 };
            *reinterpret_cast<float2*>(&C[(size_t)row * Ntot + col]) = v0;
            *reinterpret_cast<float2*>(&C[(size_t)(row + 8) * Ntot + col]) = v1;
        }
    }
}

// ======================= tensor-core flash attention ========================
// grid (12, 256), block 352 (11 warps). Warp owns 32 query rows (2 m16 tiles).
// KV chunks of 64 keys. m16n8k8 tf32 mma for S=QK^T (+bias init) and O=PV.
#define AT_THREADS 352
#define LDKV 40     // K/V smem stride: conflict-free b-frag loads
#define LDP  36     // per-warp P/Q smem stride: conflict-free a-frag loads
#define AT_SMEM ((2 * 64 * LDKV + 11 * 32 * LDP) * 4)   // 71168 B

__global__ __launch_bounds__(AT_THREADS, 1) void attn_mma_kernel(
    const float* __restrict__ qkv, const float* __restrict__ biasP,
    float* __restrict__ out)
{
    extern __shared__ float sm[];
    float* Ks = sm;                 // [64][LDKV]
    float* Vs = sm + 64 * LDKV;     // [64][LDKV]
    const int h   = blockIdx.x;
    const int b   = blockIdx.y;
    const int tid = threadIdx.x;
    const int wid = tid >> 5, lid = tid & 31;
    const int g = lid >> 2, t4 = lid & 3;
    float* Pw = sm + 2 * 64 * LDKV + wid * (32 * LDP);   // warp-private
    const int wm = wid * 32;
    const float* base = qkv + (size_t)b * NTOK * QKVC;
    const float scale = 0.17677669529663687f;

    // ---- stage this warp's Q rows into Pw, then extract scaled tf32 a-frags
#pragma unroll
    for (int i = 0; i < 8; ++i) {
        int f = lid + i * 32;
        int row = f >> 3, c4 = (f & 7) * 4;
        int qrow = wm + row;
        float4 v = make_float4(0.f, 0.f, 0.f, 0.f);
        if (qrow < NTOK)
            v = *reinterpret_cast<const float4*>(base + (size_t)qrow * QKVC + h * HDIM + c4);
        Pw[row * LDP + c4 + 0] = v.x;
        Pw[row * LDP + c4 + 1] = v.y;
        Pw[row * LDP + c4 + 2] = v.z;
        Pw[row * LDP + c4 + 3] = v.w;
    }
    __syncwarp();

    uint32_t qa[2][4][4];
#pragma unroll
    for (int mi = 0; mi < 2; ++mi)
#pragma unroll
        for (int ks = 0; ks < 4; ++ks) {
            const int r0 = (mi * 16 + g) * LDP, r1 = (mi * 16 + 8 + g) * LDP;
            const int k = ks * 8 + t4;
            qa[mi][ks][0] = tf32u(Pw[r0 + k] * scale);
            qa[mi][ks][1] = tf32u(Pw[r1 + k] * scale);
            qa[mi][ks][2] = tf32u(Pw[r0 + k + 4] * scale);
            qa[mi][ks][3] = tf32u(Pw[r1 + k + 4] * scale);
        }

    float o[2][4][4];
#pragma unroll
    for (int mi = 0; mi < 2; ++mi)
#pragma unroll
        for (int n = 0; n < 4; ++n)
#pragma unroll
            for (int q = 0; q < 4; ++q) o[mi][n][q] = 0.f;
    float mrow[2][2] = {{-1e30f, -1e30f}, {-1e30f, -1e30f}};
    float lrow[2][2] = {{0.f, 0.f}, {0.f, 0.f}};

    const float* bp = biasP + ((size_t)h * NPAD + wm) * KPAD;

    for (int ch = 0; ch < 6; ++ch) {
        const int j0 = ch * 64;
        __syncthreads();
        // ---- cooperative K/V chunk load (round to tf32, zero-pad) ---------
#pragma unroll
        for (int i = 0; i < 2; ++i) {
            int f = tid + i * AT_THREADS;
            if (f < 512) {
                int row = f >> 3, c4 = (f & 7) * 4;
                int kr = j0 + row;
                float4 kv = make_float4(0.f, 0.f, 0.f, 0.f);
                float4 vv = make_float4(0.f, 0.f, 0.f, 0.f);
                if (kr < NTOK) {
                    const float* rp = base + (size_t)kr * QKVC + h * HDIM;
                    kv = *reinterpret_cast<const float4*>(rp + CDIM + c4);
                    vv = *reinterpret_cast<const float4*>(rp + 2 * CDIM + c4);
                }
                float4 kr4 = { tf32_rna(kv.x), tf32_rna(kv.y), tf32_rna(kv.z), tf32_rna(kv.w) };
                float4 vr4 = { tf32_rna(vv.x), tf32_rna(vv.y), tf32_rna(vv.z), tf32_rna(vv.w) };
                *reinterpret_cast<float4*>(&Ks[row * LDKV + c4]) = kr4;
                *reinterpret_cast<float4*>(&Vs[row * LDKV + c4]) = vr4;
            }
        }
        __syncthreads();

        // ---- S accumulators initialized from padded bias ------------------
        float c[2][8][4];
#pragma unroll
        for (int mi = 0; mi < 2; ++mi) {
            const float* b0p = bp + (size_t)(mi * 16 + g) * KPAD + j0 + 2 * t4;
            const float* b1p = bp + (size_t)(mi * 16 + 8 + g) * KPAD + j0 + 2 * t4;
#pragma unroll
            for (int ni = 0; ni < 8; ++ni) {
                float2 v0 = *reinterpret_cast<const float2*>(b0p + ni * 8);
                float2 v1 = *reinterpret_cast<const float2*>(b1p + ni * 8);
                c[mi][ni][0] = v0.x; c[mi][ni][1] = v0.y;
                c[mi][ni][2] = v1.x; c[mi][ni][3] = v1.y;
            }
        }
        // ---- S += Q K^T ---------------------------------------------------
#pragma unroll
        for (int ks = 0; ks < 4; ++ks) {
            const int k = ks * 8 + t4;
            uint32_t kb[8][2];
#pragma unroll
            for (int ni = 0; ni < 8; ++ni) {
                kb[ni][0] = __float_as_uint(Ks[(ni * 8 + g) * LDKV + k]);
                kb[ni][1] = __float_as_uint(Ks[(ni * 8 + g) * LDKV + k + 4]);
            }
#pragma unroll
            for (int mi = 0; mi < 2; ++mi)
#pragma unroll
                for (int ni = 0; ni < 8; ++ni)
                    mma_tf32(c[mi][ni], qa[mi][ks], kb[ni]);
        }

        // ---- online softmax ----------------------------------------------
#pragma unroll
        for (int mi = 0; mi < 2; ++mi) {
            float mx0 = c[mi][0][0], mx1 = c[mi][0][2];
#pragma unroll
            for (int ni = 0; ni < 8; ++ni) {
                mx0 = fmaxf(mx0, fmaxf(c[mi][ni][0], c[mi][ni][1]));
                mx1 = fmaxf(mx1, fmaxf(c[mi][ni][2], c[mi][ni][3]));
            }
            mx0 = fmaxf(mx0, __shfl_xor_sync(0xFFFFFFFF, mx0, 1));
            mx0 = fmaxf(mx0, __shfl_xor_sync(0xFFFFFFFF, mx0, 2));
            mx1 = fmaxf(mx1, __shfl_xor_sync(0xFFFFFFFF, mx1, 1));
            mx1 = fmaxf(mx1, __shfl_xor_sync(0xFFFFFFFF, mx1, 2));
            float nm0 = fmaxf(mrow[mi][0], mx0);
            float nm1 = fmaxf(mrow[mi][1], mx1);
            float cr0 = __expf(mrow[mi][0] - nm0);
            float cr1 = __expf(mrow[mi][1] - nm1);
            mrow[mi][0] = nm0; mrow[mi][1] = nm1;
#pragma unroll
            for (int n = 0; n < 4; ++n) {
                o[mi][n][0] *= cr0; o[mi][n][1] *= cr0;
                o[mi][n][2] *= cr1; o[mi][n][3] *= cr1;
            }
            float s0 = 0.f, s1 = 0.f;
#pragma unroll
            for (int ni = 0; ni < 8; ++ni) {
                c[mi][ni][0] = __expf(c[mi][ni][0] - nm0); s0 += c[mi][ni][0];
                c[mi][ni][1] = __expf(c[mi][ni][1] - nm0); s0 += c[mi][ni][1];
                c[mi][ni][2] = __expf(c[mi][ni][2] - nm1); s1 += c[mi][ni][2];
                c[mi][ni][3] = __expf(c[mi][ni][3] - nm1); s1 += c[mi][ni][3];
            }
            s0 += __shfl_xor_sync(0xFFFFFFFF, s0, 1);
            s0 += __shfl_xor_sync(0xFFFFFFFF, s0, 2);
            s1 += __shfl_xor_sync(0xFFFFFFFF, s1, 1);
            s1 += __shfl_xor_sync(0xFFFFFFFF, s1, 2);
            lrow[mi][0] = lrow[mi][0] * cr0 + s0;
            lrow[mi][1] = lrow[mi][1] * cr1 + s1;
        }

        // ---- O += P V : groups of 16 keys via warp-private smem -----------
#pragma unroll
        for (int grp = 0; grp < 4; ++grp) {
#pragma unroll
            for (int mi = 0; mi < 2; ++mi)
#pragma unroll
                for (int q = 0; q < 2; ++q) {
                    const int nt = 2 * grp + q;
                    float2 p0 = { tf32_rna(c[mi][nt][0]), tf32_rna(c[mi][nt][1]) };
                    float2 p1 = { tf32_rna(c[mi][nt][2]), tf32_rna(c[mi][nt][3]) };
                    *reinterpret_cast<float2*>(&Pw[(mi * 16 + g) * LDP + q * 8 + 2 * t4]) = p0;
                    *reinterpret_cast<float2*>(&Pw[(mi * 16 + 8 + g) * LDP + q * 8 + 2 * t4]) = p1;
                }
            __syncwarp();
#pragma unroll
            for (int ks2 = 0; ks2 < 2; ++ks2) {
                uint32_t pa[2][4];
#pragma unroll
                for (int mi = 0; mi < 2; ++mi) {
                    const int r0 = (mi * 16 + g) * LDP, r1 = (mi * 16 + 8 + g) * LDP;
                    const int k = ks2 * 8 + t4;
                    pa[mi][0] = __float_as_uint(Pw[r0 + k]);
                    pa[mi][1] = __float_as_uint(Pw[r1 + k]);
                    pa[mi][2] = __float_as_uint(Pw[r0 + k + 4]);
                    pa[mi][3] = __float_as_uint(Pw[r1 + k + 4]);
                }
                uint32_t vb[4][2];
                const int kr = grp * 16 + ks2 * 8;
#pragma unroll
                for (int n = 0; n < 4; ++n) {
                    vb[n][0] = __float_as_uint(Vs[(kr + t4) * LDKV + n * 8 + g]);
                    vb[n][1] = __float_as_uint(Vs[(kr + t4 + 4) * LDKV + n * 8 + g]);
                }
#pragma unroll
                for (int mi = 0; mi < 2; ++mi)
#pragma unroll
                    for (int n = 0; n < 4; ++n)
                        mma_tf32(o[mi][n], pa[mi], vb[n]);
            }
            __syncwarp();
        }
    }

    // ---- normalize + store (tf32-rounded for proj GEMM input) -------------
#pragma unroll
    for (int mi = 0; mi < 2; ++mi) {
        const float i0 = 1.f / lrow[mi][0];
        const float i1 = 1.f / lrow[mi][1];
        const int r0 = wm + mi * 16 + g;
        const int r1 = r0 + 8;
        if (r0 < NTOK) {
            float* op = out + ((size_t)b * NTOK + r0) * CDIM + h * HDIM + 2 * t4;
#pragma unroll
            for (int n = 0; n < 4; ++n) {
                float2 v = { tf32_rna(o[mi][n][0] * i0), tf32_rna(o[mi][n][1] * i0) };
                *reinterpret_cast<float2*>(op + n * 8) = v;
            }
        }
        if (r1 < NTOK) {
            float* op = out + ((size_t)b * NTOK + r1) * CDIM + h * HDIM + 2 * t4;
#pragma unroll
            for (int n = 0; n < 4; ++n) {
                float2 v = { tf32_rna(o[mi][n][2] * i1), tf32_rna(o[mi][n][3] * i1) };
                *reinterpret_cast<float2*>(op + n * 8) = v;
            }
        }
    }
}

// ---------------- launch ------------------------------------------------------
extern "C" void kernel_launch(void* const* d_in, const int* in_sizes, int n_in,
                              void* d_out, int out_size)
{
    const float* x       = (const float*)d_in[0];
    const float* qkv_w   = (const float*)d_in[1];
    const float* qkv_b   = (const float*)d_in[2];
    const float* proj_w  = (const float*)d_in[3];
    const float* proj_b  = (const float*)d_in[4];
    const float* bt      = (const float*)d_in[5];
    const int*   ridx    = (const int*)d_in[6];
    float*       out     = (float*)d_out;

    void *p_qkv, *p_att, *p_bias, *p_xr, *p_wqt, *p_wpt;
    cudaGetSymbolAddress(&p_qkv,  g_qkv);
    cudaGetSymbolAddress(&p_att,  g_att);
    cudaGetSymbolAddress(&p_bias, g_bias);
    cudaGetSymbolAddress(&p_xr,   g_xr);
    cudaGetSymbolAddress(&p_wqt,  g_wqt);
    cudaGetSymbolAddress(&p_wpt,  g_wpt);
    float* qkv  = (float*)p_qkv;
    float* att  = (float*)p_att;
    float* bias = (float*)p_bias;
    float* xr   = (float*)p_xr;
    float* wqt  = (float*)p_wqt;
    float* wpt  = (float*)p_wpt;

    cudaFuncSetAttribute(mma_gemm_kernel,
                         cudaFuncAttributeMaxDynamicSharedMemorySize, GSM_TOT);
    cudaFuncSetAttribute(attn_mma_kernel,
                         cudaFuncAttributeMaxDynamicSharedMemorySize, AT_SMEM);

    // 0) prep: tf32-round x; transpose+round weights; expand padded bias
    {
        int n4 = MROWS * CDIM / 4;
        round_tf32_kernel<<<(n4 + 255) / 256, 256>>>(x, xr, n4);
        transpose_round_kernel<<<dim3(QKVC / 32, CDIM / 32), dim3(32, 8)>>>(qkv_w, wqt, CDIM, QKVC);
        transpose_round_kernel<<<dim3(CDIM / 32, CDIM / 32), dim3(32, 8)>>>(proj_w, wpt, CDIM, CDIM);
        int total = NHEADS * NPAD * KPAD;
        bias_expand_pad_kernel<<<(total + 255) / 256, 256>>>(bt, ridx, bias);
    }

    // 1) QKV projection (mma.sync tf32)
    mma_gemm_kernel<<<dim3(QKVC / 128, MROWS / 128), 256, GSM_TOT>>>(xr, wqt, qkv_b, qkv, QKVC);

    // 2) tensor-core flash attention (QK^T + bias + softmax + PV)
    attn_mma_kernel<<<dim3(NHEADS, NWIN), AT_THREADS, AT_SMEM>>>(qkv, bias, att);

    // 3) output projection (mma.sync tf32)
    mma_gemm_kernel<<<dim3(CDIM / 128, MROWS / 128), 256, GSM_TOT>>>(att, wpt, proj_b, out, CDIM);
}